// round 1
// baseline (speedup 1.0000x reference)
#include <cuda_runtime.h>
#include <math.h>

// ---------------- problem constants ----------------
static constexpr int kBS = 2;
static constexpr int kC  = 128;
static constexpr int kH  = 80;
static constexpr int kW  = 160;
static constexpr int kHW = kH * kW;          // 12800
static constexpr int kN  = kBS * kHW;        // 25600 pixels
static constexpr int kP  = 9;
static constexpr int kG  = 8;
static constexpr int kNOUT = 418;            // 128 vc + 128 vg + 72 wc + 72 wg + 9 kpc + 9 kpg
static constexpr int kOPAD = 432;            // padded output count (mult of 16)
static constexpr int kOUT_ELEMS = kBS * kC * kHW;      // 3,276,800
static constexpr int kKP_ELEMS  = kN * kP * 2;         // 460,800 per branch

// ---------------- scratch (device globals; no allocation) ----------------
__device__ float g_vals_ctx[kN * kC];        // pixel-major ctx value features
__device__ float g_vals_geo[kN * kC];
__device__ float g_w_ctx[kN * 72];           // raw (pre-softmax) attention logits
__device__ float g_w_geo[kN * 72];
__device__ float g_kp[2 * kN * kP * 2];      // keypoints per branch
__device__ float g_WgT[128 * kOPAD];         // k-major fused (gamma-scaled) weights
__device__ float g_Rs[kOPAD];                // rowsum of gamma-scaled weights
__device__ float g_Bt[kOPAD];                // W@beta + bias
__device__ float g_OWT[256 * 128];           // transposed out_w (k-major)

// ---------------- prep kernel 1: build fused LN+conv weights ----------------
__global__ void prep_weights(
    const float* __restrict__ vc_w, const float* __restrict__ vc_b,
    const float* __restrict__ vg_w, const float* __restrict__ vg_b,
    const float* __restrict__ wc_w, const float* __restrict__ wc_b,
    const float* __restrict__ wg_w, const float* __restrict__ wg_b,
    const float* __restrict__ kpc_w, const float* __restrict__ kpc_b,
    const float* __restrict__ kpg_w, const float* __restrict__ kpg_b,
    const float* __restrict__ ln_g, const float* __restrict__ ln_b,
    const float* __restrict__ lnc_g, const float* __restrict__ lnc_b,
    const float* __restrict__ lng_g, const float* __restrict__ lng_b)
{
    __shared__ float r1[4], r2[4];
    const int o = blockIdx.x;
    const int k = threadIdx.x;   // 128 threads
    if (o >= kNOUT) {
        g_WgT[k * kOPAD + o] = 0.f;
        if (k == 0) { g_Rs[o] = 0.f; g_Bt[o] = 0.f; }
        return;
    }
    const float* Wrow; float bias; const float* ga; const float* be;
    if (o < 128)      { Wrow = vc_w  + o * 128;         bias = vc_b[o];        ga = lnc_g; be = lnc_b; }
    else if (o < 256) { Wrow = vg_w  + (o - 128) * 128; bias = vg_b[o - 128];  ga = lng_g; be = lng_b; }
    else if (o < 328) { Wrow = wc_w  + (o - 256) * 128; bias = wc_b[o - 256];  ga = ln_g;  be = ln_b;  }
    else if (o < 400) { Wrow = wg_w  + (o - 328) * 128; bias = wg_b[o - 328];  ga = ln_g;  be = ln_b;  }
    else if (o < 409) { Wrow = kpc_w + (o - 400) * 128; bias = kpc_b[o - 400]; ga = ln_g;  be = ln_b;  }
    else              { Wrow = kpg_w + (o - 409) * 128; bias = kpg_b[o - 409]; ga = ln_g;  be = ln_b;  }
    const float w  = Wrow[k];
    const float wg = w * ga[k];
    g_WgT[k * kOPAD + o] = wg;
    float s1 = wg, s2 = w * be[k];
    #pragma unroll
    for (int off = 16; off; off >>= 1) {
        s1 += __shfl_down_sync(0xffffffffu, s1, off);
        s2 += __shfl_down_sync(0xffffffffu, s2, off);
    }
    if ((k & 31) == 0) { r1[k >> 5] = s1; r2[k >> 5] = s2; }
    __syncthreads();
    if (k == 0) {
        g_Rs[o] = r1[0] + r1[1] + r1[2] + r1[3];
        g_Bt[o] = r2[0] + r2[1] + r2[2] + r2[3] + bias;
    }
}

// ---------------- prep kernel 2: transpose out_w ----------------
__global__ void prep_outw(const float* __restrict__ out_w)
{
    const int k = blockIdx.x;    // 0..255
    const int o = threadIdx.x;   // 0..127
    g_OWT[k * 128 + o] = out_w[o * 256 + k];
}

// ---------------- kernel 1: LN-fused GEMMs over all 418 outputs ----------------
__device__ __forceinline__ void gemm_tile(const float* __restrict__ xsb,
                                          const float* __restrict__ wb,
                                          float acc[4][4])
{
    #pragma unroll
    for (int i = 0; i < 4; i++)
        #pragma unroll
        for (int j = 0; j < 4; j++) acc[i][j] = 0.f;
    #pragma unroll 8
    for (int k = 0; k < 128; k++) {
        const float4 xv = *reinterpret_cast<const float4*>(xsb + k * 32);
        const float4 wv = *reinterpret_cast<const float4*>(wb + k * kOPAD);
        const float xa[4] = {xv.x, xv.y, xv.z, xv.w};
        const float wa[4] = {wv.x, wv.y, wv.z, wv.w};
        #pragma unroll
        for (int i = 0; i < 4; i++)
            #pragma unroll
            for (int j = 0; j < 4; j++)
                acc[i][j] = fmaf(wa[i], xa[j], acc[i][j]);
    }
}

__global__ __launch_bounds__(256) void k1_ln_gemm(
    const float* __restrict__ match, const float* __restrict__ context,
    const float* __restrict__ geometric,
    const float* __restrict__ anc_c, const float* __restrict__ anc_g,
    float* __restrict__ d_out, int out_size)
{
    extern __shared__ float sm[];
    float* xs      = sm;                 // [3][128][32]
    float* mean_sm = sm + 3 * 128 * 32;  // [3][32]
    float* istd_sm = mean_sm + 96;       // [3][32]

    const int t   = threadIdx.x;
    const int nb  = blockIdx.x * 32;
    const int b   = nb / kHW;
    const int hwb = nb - b * kHW;

    // stage 32 pixels x 128 channels for the 3 source tensors
    {
        const int px = t & 31, c0 = t >> 5;
        const float* srcs[3] = {match, context, geometric};
        #pragma unroll
        for (int s = 0; s < 3; s++) {
            const float* gp = srcs[s] + b * kC * kHW + hwb + px;
            float* xp = xs + s * 4096 + px;
            #pragma unroll
            for (int c = c0; c < 128; c += 8) xp[c * 32] = gp[c * kHW];
        }
    }
    __syncthreads();

    // per-pixel LN stats for each source
    if (t < 96) {
        const int s = t >> 5, p = t & 31;
        const float* xp = xs + s * 4096 + p;
        float su = 0.f, sq = 0.f;
        #pragma unroll
        for (int k = 0; k < 128; k++) { const float v = xp[k * 32]; su += v; sq += v * v; }
        const float m   = su * (1.f / 128.f);
        const float var = sq * (1.f / 128.f) - m * m;
        mean_sm[t] = m;
        istd_sm[t] = rsqrtf(var + 1e-5f);
    }
    __syncthreads();

    const int ty = t >> 3, tx = t & 7;
    const int px0 = tx * 4;
    float acc[4][4], v[4][4];

    auto normalize = [&](int src, int o0) {
        float m4[4], i4[4];
        #pragma unroll
        for (int j = 0; j < 4; j++) { m4[j] = mean_sm[src * 32 + px0 + j]; i4[j] = istd_sm[src * 32 + px0 + j]; }
        #pragma unroll
        for (int i = 0; i < 4; i++) {
            const float rs = g_Rs[o0 + i], bt = g_Bt[o0 + i];
            #pragma unroll
            for (int j = 0; j < 4; j++)
                v[i][j] = (acc[i][j] - m4[j] * rs) * i4[j] + bt;
        }
    };

    // pass 1: vc (source = context) -> g_vals_ctx
    {
        const int o0 = ty * 4;
        gemm_tile(xs + 1 * 4096 + px0, g_WgT + o0, acc);
        normalize(1, o0);
        #pragma unroll
        for (int j = 0; j < 4; j++) {
            const int n = nb + px0 + j;
            *reinterpret_cast<float4*>(&g_vals_ctx[n * kC + o0]) =
                make_float4(v[0][j], v[1][j], v[2][j], v[3][j]);
        }
    }
    // pass 2: vg (source = geometric) -> g_vals_geo
    {
        const int o0 = 128 + ty * 4;
        gemm_tile(xs + 2 * 4096 + px0, g_WgT + o0, acc);
        normalize(2, o0);
        #pragma unroll
        for (int j = 0; j < 4; j++) {
            const int n = nb + px0 + j;
            *reinterpret_cast<float4*>(&g_vals_geo[n * kC + (o0 - 128)]) =
                make_float4(v[0][j], v[1][j], v[2][j], v[3][j]);
        }
    }
    // pass 3: wc / wg logits (source = match)
    {
        const int o0 = 256 + ty * 4;
        gemm_tile(xs + px0, g_WgT + o0, acc);
        normalize(0, o0);
        const int j0 = o0 - 256;
        float* dst; int col;
        if (j0 < 72) { dst = g_w_ctx; col = j0; } else { dst = g_w_geo; col = j0 - 72; }
        #pragma unroll
        for (int j = 0; j < 4; j++) {
            const int n = nb + px0 + j;
            *reinterpret_cast<float4*>(&dst[n * 72 + col]) =
                make_float4(v[0][j], v[1][j], v[2][j], v[3][j]);
        }
    }
    // pass 4: rest of wg + keypoint offsets (source = match)
    {
        const int o0 = 384 + ty * 4;
        if (o0 < kNOUT) {
            gemm_tile(xs + px0, g_WgT + o0, acc);
            normalize(0, o0);
            if (o0 < 400) {  // still wg
                const int col = o0 - 328;
                #pragma unroll
                for (int j = 0; j < 4; j++) {
                    const int n = nb + px0 + j;
                    *reinterpret_cast<float4*>(&g_w_geo[n * 72 + col]) =
                        make_float4(v[0][j], v[1][j], v[2][j], v[3][j]);
                }
            } else {         // keypoints, elementwise (not 4-aligned across branches)
                #pragma unroll
                for (int i = 0; i < 4; i++) {
                    const int o = o0 + i;
                    if (o >= kNOUT) break;
                    const int br = (o < 409) ? 0 : 1;
                    const int p = o - (br ? 409 : 400);
                    const float* anc = br ? anc_g : anc_c;
                    float* outkp = (out_size >= kOUT_ELEMS + 2 * kKP_ELEMS)
                                   ? (d_out + kOUT_ELEMS + br * kKP_ELEMS) : nullptr;
                    #pragma unroll
                    for (int j = 0; j < 4; j++) {
                        const int n = nb + px0 + j;
                        const int ai = (n * kP + p) * 2;
                        const float kx = anc[ai] + v[i][j];
                        const float ky = anc[ai + 1];
                        g_kp[br * (kN * kP * 2) + ai]     = kx;
                        g_kp[br * (kN * kP * 2) + ai + 1] = ky;
                        if (outkp) { outkp[ai] = kx; outkp[ai + 1] = ky; }
                    }
                }
            }
        }
    }
}

// ---------------- kernel 2: softmax + deformable gather + output conv ----------------
__global__ __launch_bounds__(256) void k2_aggregate(
    const float* __restrict__ mask, const float* __restrict__ out_b,
    float* __restrict__ d_out)
{
    extern __shared__ float sm[];
    float* wts  = sm;                       // [32][144]  (softmax weights, c = p*8+g)
    float* cw   = sm + 4608;                // [32][18][4] corner weights
    int*   cidx = (int*)(sm + 6912);        // [32][18][4] corner pixel indices
    float* feat = sm + 9216;                // [256][33]  aggregated features (k-major)
    float* msm  = sm + 17664;               // [32] mask

    const int t   = threadIdx.x;
    const int nb  = blockIdx.x * 32;
    const int b   = nb / kHW;
    const int hwb = nb - b * kHW;

    // load raw logits (contiguous) + mask
    for (int idx = t; idx < 2304; idx += 256) {
        const int px = idx / 72, j = idx - px * 72;
        wts[px * 144 + j]      = g_w_ctx[nb * 72 + idx];
        wts[px * 144 + 72 + j] = g_w_geo[nb * 72 + idx];
    }
    if (t < 32) msm[t] = mask[b * kHW + hwb + t];
    __syncthreads();

    // softmax over p for each (px, branch, group): 32*16 = 512 tasks
    for (int task = t; task < 512; task += 256) {
        const int px = task >> 4, bg = task & 15;
        float* base = wts + px * 144 + (bg >> 3) * 72 + (bg & 7);
        float mx = base[0];
        #pragma unroll
        for (int p = 1; p < kP; p++) mx = fmaxf(mx, base[p * 8]);
        float s = 0.f;
        #pragma unroll
        for (int p = 0; p < kP; p++) { const float e = __expf(base[p * 8] - mx); base[p * 8] = e; s += e; }
        const float inv = 1.f / s;
        #pragma unroll
        for (int p = 0; p < kP; p++) base[p * 8] *= inv;
    }

    // bilinear corner precompute: 32*18 = 576 tasks
    for (int task = t; task < 576; task += 256) {
        const int px = task / 18, j = task - px * 18;
        const int br = j / 9, p = j - br * 9;
        const int n = nb + px;
        const float* kp = g_kp + br * (kN * kP * 2) + (n * kP + p) * 2;
        const float x = kp[0] * (float)kW - 0.5f;
        const float y = kp[1] * (float)kH - 0.5f;
        const float xf = floorf(x), yf = floorf(y);
        const float dx = x - xf, dy = y - yf;
        const int x0 = (int)xf, y0 = (int)yf;
        const int o = (px * 18 + j) * 4;
        #pragma unroll
        for (int c = 0; c < 4; c++) {
            const int xi = x0 + (c & 1), yi = y0 + (c >> 1);
            const bool valid = (xi >= 0) && (xi < kW) && (yi >= 0) && (yi < kH);
            const int xc = min(max(xi, 0), kW - 1), yc = min(max(yi, 0), kH - 1);
            const float wt = ((c & 1) ? dx : 1.f - dx) * ((c >> 1) ? dy : 1.f - dy);
            cw[o + c]   = valid ? wt : 0.f;
            cidx[o + c] = yc * kW + xc;
        }
    }
    __syncthreads();

    // phase 1: deformable gather.  t -> (pq 0..3, br 0..1, c4 0..31)
    {
        const int c4 = t & 31;
        const int br = (t >> 5) & 1;
        const int pq = t >> 6;
        const float* vals = (br ? g_vals_geo : g_vals_ctx) + b * kHW * kC + c4 * 4;
        const int gidx = c4 >> 2;  // group = (c4*4)/16
        #pragma unroll
        for (int chunk = 0; chunk < 8; chunk++) {
            const int px = chunk * 4 + pq;
            float a0 = 0.f, a1 = 0.f, a2 = 0.f, a3 = 0.f;
            const float* wtp = wts + px * 144 + br * 72 + gidx;
            const float* cwp = cw + (px * 18 + br * 9) * 4;
            const int*   idp = cidx + (px * 18 + br * 9) * 4;
            #pragma unroll
            for (int p = 0; p < kP; p++) {
                const float wp = wtp[p * 8];
                #pragma unroll
                for (int c = 0; c < 4; c++) {
                    const float f = wp * cwp[p * 4 + c];
                    const float4 vv = *reinterpret_cast<const float4*>(vals + idp[p * 4 + c] * kC);
                    a0 = fmaf(f, vv.x, a0); a1 = fmaf(f, vv.y, a1);
                    a2 = fmaf(f, vv.z, a2); a3 = fmaf(f, vv.w, a3);
                }
            }
            const float sc = br ? 1.f : msm[px];
            float* fb = feat + (br * 128 + c4 * 4) * 33 + px;
            fb[0]  = a0 * sc; fb[33] = a1 * sc;
            fb[66] = a2 * sc; fb[99] = a3 * sc;
        }
    }
    __syncthreads();

    // phase 2: 256 -> 128 output conv, 4x4 register tiles
    {
        const int ty = t >> 3, tx = t & 7;
        const int o0 = ty * 4, px0 = tx * 4;
        float acc[4][4];
        #pragma unroll
        for (int i = 0; i < 4; i++)
            #pragma unroll
            for (int j = 0; j < 4; j++) acc[i][j] = 0.f;
        #pragma unroll 8
        for (int k = 0; k < 256; k++) {
            const float4 wv = *reinterpret_cast<const float4*>(g_OWT + k * 128 + o0);
            const float* fr = feat + k * 33 + px0;
            const float fa[4] = {fr[0], fr[1], fr[2], fr[3]};
            const float wa[4] = {wv.x, wv.y, wv.z, wv.w};
            #pragma unroll
            for (int i = 0; i < 4; i++)
                #pragma unroll
                for (int j = 0; j < 4; j++)
                    acc[i][j] = fmaf(wa[i], fa[j], acc[i][j]);
        }
        #pragma unroll
        for (int i = 0; i < 4; i++) {
            const float bb = out_b[o0 + i];
            *reinterpret_cast<float4*>(d_out + b * kC * kHW + (o0 + i) * kHW + hwb + px0) =
                make_float4(acc[i][0] + bb, acc[i][1] + bb, acc[i][2] + bb, acc[i][3] + bb);
        }
    }
}

// ---------------- launch ----------------
extern "C" void kernel_launch(void* const* d_in, const int* in_sizes, int n_in,
                              void* d_out, int out_size)
{
    const float* mask      = (const float*)d_in[0];
    const float* match     = (const float*)d_in[1];
    const float* context   = (const float*)d_in[2];
    const float* geometric = (const float*)d_in[3];
    const float* anc_c     = (const float*)d_in[4];
    const float* anc_g     = (const float*)d_in[5];
    const float* ln_g  = (const float*)d_in[6];
    const float* ln_b  = (const float*)d_in[7];
    const float* lnc_g = (const float*)d_in[8];
    const float* lnc_b = (const float*)d_in[9];
    const float* lng_g = (const float*)d_in[10];
    const float* lng_b = (const float*)d_in[11];
    const float* wc_w  = (const float*)d_in[12];
    const float* wc_b  = (const float*)d_in[13];
    const float* wg_w  = (const float*)d_in[14];
    const float* wg_b  = (const float*)d_in[15];
    const float* vc_w  = (const float*)d_in[16];
    const float* vc_b  = (const float*)d_in[17];
    const float* vg_w  = (const float*)d_in[18];
    const float* vg_b  = (const float*)d_in[19];
    const float* out_w = (const float*)d_in[20];
    const float* out_b = (const float*)d_in[21];
    const float* kpc_w = (const float*)d_in[22];
    const float* kpc_b = (const float*)d_in[23];
    const float* kpg_w = (const float*)d_in[24];
    const float* kpg_b = (const float*)d_in[25];
    float* out = (float*)d_out;

    cudaFuncSetAttribute(k1_ln_gemm, cudaFuncAttributeMaxDynamicSharedMemorySize, 50176);
    cudaFuncSetAttribute(k2_aggregate, cudaFuncAttributeMaxDynamicSharedMemorySize, 71680);

    prep_weights<<<kOPAD, 128>>>(vc_w, vc_b, vg_w, vg_b, wc_w, wc_b, wg_w, wg_b,
                                 kpc_w, kpc_b, kpg_w, kpg_b,
                                 ln_g, ln_b, lnc_g, lnc_b, lng_g, lng_b);
    prep_outw<<<256, 128>>>(out_w);
    k1_ln_gemm<<<kN / 32, 256, 49920>>>(match, context, geometric, anc_c, anc_g, out, out_size);
    k2_aggregate<<<kN / 32, 256, 70784>>>(mask, out_b, out);
}

// round 2
// speedup vs baseline: 1.3913x; 1.3913x over previous
#include <cuda_runtime.h>
#include <cuda_fp16.h>
#include <math.h>

// ---------------- problem constants ----------------
static constexpr int kBS = 2;
static constexpr int kC  = 128;
static constexpr int kH  = 80;
static constexpr int kW  = 160;
static constexpr int kHW = kH * kW;          // 12800
static constexpr int kN  = kBS * kHW;        // 25600 pixels
static constexpr int kP  = 9;
static constexpr int kG  = 8;
static constexpr int kNOUT = 418;            // 128 vc + 128 vg + 72 wc + 72 wg + 9 kpc + 9 kpg
static constexpr int kOPAD = 432;            // padded output count (mult of 16)
static constexpr int kOUT_ELEMS = kBS * kC * kHW;      // 3,276,800
static constexpr int kKP_ELEMS  = kN * kP * 2;         // 460,800 per branch

struct __align__(8) H4 { __half2 a, b; };

// ---------------- scratch (device globals; no allocation) ----------------
__device__ __align__(16) __half g_vals_ctx[kN * kC];   // pixel-major ctx value features (fp16)
__device__ __align__(16) __half g_vals_geo[kN * kC];
__device__ float g_w_ctx[kN * 72];           // raw (pre-softmax) attention logits
__device__ float g_w_geo[kN * 72];
__device__ float g_kp[2 * kN * kP * 2];      // keypoints per branch
__device__ float g_WgT[128 * kOPAD];         // k-major fused (gamma-scaled) weights
__device__ float g_Rs[kOPAD];                // rowsum of gamma-scaled weights
__device__ float g_Bt[kOPAD];                // W@beta + bias
__device__ float g_OWT[256 * 128];           // transposed out_w (k-major)

// ---------------- prep kernel 1: build fused LN+conv weights ----------------
__global__ void prep_weights(
    const float* __restrict__ vc_w, const float* __restrict__ vc_b,
    const float* __restrict__ vg_w, const float* __restrict__ vg_b,
    const float* __restrict__ wc_w, const float* __restrict__ wc_b,
    const float* __restrict__ wg_w, const float* __restrict__ wg_b,
    const float* __restrict__ kpc_w, const float* __restrict__ kpc_b,
    const float* __restrict__ kpg_w, const float* __restrict__ kpg_b,
    const float* __restrict__ ln_g, const float* __restrict__ ln_b,
    const float* __restrict__ lnc_g, const float* __restrict__ lnc_b,
    const float* __restrict__ lng_g, const float* __restrict__ lng_b)
{
    __shared__ float r1[4], r2[4];
    const int o = blockIdx.x;
    const int k = threadIdx.x;   // 128 threads
    if (o >= kNOUT) {
        g_WgT[k * kOPAD + o] = 0.f;
        if (k == 0) { g_Rs[o] = 0.f; g_Bt[o] = 0.f; }
        return;
    }
    const float* Wrow; float bias; const float* ga; const float* be;
    if (o < 128)      { Wrow = vc_w  + o * 128;         bias = vc_b[o];        ga = lnc_g; be = lnc_b; }
    else if (o < 256) { Wrow = vg_w  + (o - 128) * 128; bias = vg_b[o - 128];  ga = lng_g; be = lng_b; }
    else if (o < 328) { Wrow = wc_w  + (o - 256) * 128; bias = wc_b[o - 256];  ga = ln_g;  be = ln_b;  }
    else if (o < 400) { Wrow = wg_w  + (o - 328) * 128; bias = wg_b[o - 328];  ga = ln_g;  be = ln_b;  }
    else if (o < 409) { Wrow = kpc_w + (o - 400) * 128; bias = kpc_b[o - 400]; ga = ln_g;  be = ln_b;  }
    else              { Wrow = kpg_w + (o - 409) * 128; bias = kpg_b[o - 409]; ga = ln_g;  be = ln_b;  }
    const float w  = Wrow[k];
    const float wg = w * ga[k];
    g_WgT[k * kOPAD + o] = wg;
    float s1 = wg, s2 = w * be[k];
    #pragma unroll
    for (int off = 16; off; off >>= 1) {
        s1 += __shfl_down_sync(0xffffffffu, s1, off);
        s2 += __shfl_down_sync(0xffffffffu, s2, off);
    }
    if ((k & 31) == 0) { r1[k >> 5] = s1; r2[k >> 5] = s2; }
    __syncthreads();
    if (k == 0) {
        g_Rs[o] = r1[0] + r1[1] + r1[2] + r1[3];
        g_Bt[o] = r2[0] + r2[1] + r2[2] + r2[3] + bias;
    }
}

// ---------------- prep kernel 2: transpose out_w ----------------
__global__ void prep_outw(const float* __restrict__ out_w)
{
    const int k = blockIdx.x;    // 0..255
    const int o = threadIdx.x;   // 0..127
    g_OWT[k * 128 + o] = out_w[o * 256 + k];
}

// ---------------- kernel 1: LN-fused GEMMs over all 418 outputs ----------------
__device__ __forceinline__ void gemm_tile(const float* __restrict__ xsb,
                                          const float* __restrict__ wb,
                                          float acc[4][4])
{
    #pragma unroll
    for (int i = 0; i < 4; i++)
        #pragma unroll
        for (int j = 0; j < 4; j++) acc[i][j] = 0.f;
    #pragma unroll 8
    for (int k = 0; k < 128; k++) {
        const float4 xv = *reinterpret_cast<const float4*>(xsb + k * 32);
        const float4 wv = *reinterpret_cast<const float4*>(wb + k * kOPAD);
        const float xa[4] = {xv.x, xv.y, xv.z, xv.w};
        const float wa[4] = {wv.x, wv.y, wv.z, wv.w};
        #pragma unroll
        for (int i = 0; i < 4; i++)
            #pragma unroll
            for (int j = 0; j < 4; j++)
                acc[i][j] = fmaf(wa[i], xa[j], acc[i][j]);
    }
}

__global__ __launch_bounds__(256) void k1_ln_gemm(
    const float* __restrict__ match, const float* __restrict__ context,
    const float* __restrict__ geometric,
    const float* __restrict__ anc_c, const float* __restrict__ anc_g,
    float* __restrict__ d_out, int out_size)
{
    extern __shared__ float sm[];
    float* xs      = sm;                 // [3][128][32]
    float* mean_sm = sm + 3 * 128 * 32;  // [3][32]
    float* istd_sm = mean_sm + 96;       // [3][32]

    const int t   = threadIdx.x;
    const int nb  = blockIdx.x * 32;
    const int b   = nb / kHW;
    const int hwb = nb - b * kHW;

    // stage 32 pixels x 128 channels for the 3 source tensors
    {
        const int px = t & 31, c0 = t >> 5;
        const float* srcs[3] = {match, context, geometric};
        #pragma unroll
        for (int s = 0; s < 3; s++) {
            const float* gp = srcs[s] + b * kC * kHW + hwb + px;
            float* xp = xs + s * 4096 + px;
            #pragma unroll
            for (int c = c0; c < 128; c += 8) xp[c * 32] = gp[c * kHW];
        }
    }
    __syncthreads();

    // per-pixel LN stats for each source
    if (t < 96) {
        const int s = t >> 5, p = t & 31;
        const float* xp = xs + s * 4096 + p;
        float su = 0.f, sq = 0.f;
        #pragma unroll
        for (int k = 0; k < 128; k++) { const float v = xp[k * 32]; su += v; sq += v * v; }
        const float m   = su * (1.f / 128.f);
        const float var = sq * (1.f / 128.f) - m * m;
        mean_sm[t] = m;
        istd_sm[t] = rsqrtf(var + 1e-5f);
    }
    __syncthreads();

    const int ty = t >> 3, tx = t & 7;
    const int px0 = tx * 4;
    float acc[4][4], v[4][4];

    auto normalize = [&](int src, int o0) {
        float m4[4], i4[4];
        #pragma unroll
        for (int j = 0; j < 4; j++) { m4[j] = mean_sm[src * 32 + px0 + j]; i4[j] = istd_sm[src * 32 + px0 + j]; }
        #pragma unroll
        for (int i = 0; i < 4; i++) {
            const float rs = g_Rs[o0 + i], bt = g_Bt[o0 + i];
            #pragma unroll
            for (int j = 0; j < 4; j++)
                v[i][j] = (acc[i][j] - m4[j] * rs) * i4[j] + bt;
        }
    };

    // pass 1: vc (source = context) -> g_vals_ctx (fp16)
    {
        const int o0 = ty * 4;
        gemm_tile(xs + 1 * 4096 + px0, g_WgT + o0, acc);
        normalize(1, o0);
        #pragma unroll
        for (int j = 0; j < 4; j++) {
            const int n = nb + px0 + j;
            H4 h;
            h.a = __floats2half2_rn(v[0][j], v[1][j]);
            h.b = __floats2half2_rn(v[2][j], v[3][j]);
            *reinterpret_cast<H4*>(&g_vals_ctx[n * kC + o0]) = h;
        }
    }
    // pass 2: vg (source = geometric) -> g_vals_geo (fp16)
    {
        const int o0 = 128 + ty * 4;
        gemm_tile(xs + 2 * 4096 + px0, g_WgT + o0, acc);
        normalize(2, o0);
        #pragma unroll
        for (int j = 0; j < 4; j++) {
            const int n = nb + px0 + j;
            H4 h;
            h.a = __floats2half2_rn(v[0][j], v[1][j]);
            h.b = __floats2half2_rn(v[2][j], v[3][j]);
            *reinterpret_cast<H4*>(&g_vals_geo[n * kC + (o0 - 128)]) = h;
        }
    }
    // pass 3: wc / wg logits (source = match)
    {
        const int o0 = 256 + ty * 4;
        gemm_tile(xs + px0, g_WgT + o0, acc);
        normalize(0, o0);
        const int j0 = o0 - 256;
        float* dst; int col;
        if (j0 < 72) { dst = g_w_ctx; col = j0; } else { dst = g_w_geo; col = j0 - 72; }
        #pragma unroll
        for (int j = 0; j < 4; j++) {
            const int n = nb + px0 + j;
            *reinterpret_cast<float4*>(&dst[n * 72 + col]) =
                make_float4(v[0][j], v[1][j], v[2][j], v[3][j]);
        }
    }
    // pass 4: rest of wg + keypoint offsets (source = match)
    {
        const int o0 = 384 + ty * 4;
        if (o0 < kNOUT) {
            gemm_tile(xs + px0, g_WgT + o0, acc);
            normalize(0, o0);
            if (o0 < 400) {  // still wg
                const int col = o0 - 328;
                #pragma unroll
                for (int j = 0; j < 4; j++) {
                    const int n = nb + px0 + j;
                    *reinterpret_cast<float4*>(&g_w_geo[n * 72 + col]) =
                        make_float4(v[0][j], v[1][j], v[2][j], v[3][j]);
                }
            } else {         // keypoints, elementwise (not 4-aligned across branches)
                #pragma unroll
                for (int i = 0; i < 4; i++) {
                    const int o = o0 + i;
                    if (o >= kNOUT) break;
                    const int br = (o < 409) ? 0 : 1;
                    const int p = o - (br ? 409 : 400);
                    const float* anc = br ? anc_g : anc_c;
                    float* outkp = (out_size >= kOUT_ELEMS + 2 * kKP_ELEMS)
                                   ? (d_out + kOUT_ELEMS + br * kKP_ELEMS) : nullptr;
                    #pragma unroll
                    for (int j = 0; j < 4; j++) {
                        const int n = nb + px0 + j;
                        const int ai = (n * kP + p) * 2;
                        const float kx = anc[ai] + v[i][j];
                        const float ky = anc[ai + 1];
                        g_kp[br * (kN * kP * 2) + ai]     = kx;
                        g_kp[br * (kN * kP * 2) + ai + 1] = ky;
                        if (outkp) { outkp[ai] = kx; outkp[ai + 1] = ky; }
                    }
                }
            }
        }
    }
}

// ---------------- kernel 2: softmax + deformable gather + output conv ----------------
// smem layout (bytes):
//   [0,      9216)  cw    fp32 [32][18][4]   corner weights
//   [9216,  13824)  cidx  i16  [32][18][4]   corner pixel indices
//   [13824, 23040)  wts   half [32][144]     softmax attention weights
//   [23040, 23168)  msm   fp32 [32]
//   [23168, 56960)  feat  fp32 [256][33]     aggregated features (k-major)
//                   (feat also aliased as raw-logit staging before the gather)
static constexpr int kK2Smem = 56960;

__global__ __launch_bounds__(256, 4) void k2_aggregate(
    const float* __restrict__ mask, const float* __restrict__ out_b,
    float* __restrict__ d_out)
{
    extern __shared__ unsigned char smraw[];
    float*  cw    = reinterpret_cast<float*>(smraw);
    short*  cidx  = reinterpret_cast<short*>(smraw + 9216);
    __half* wts   = reinterpret_cast<__half*>(smraw + 13824);
    float*  msm   = reinterpret_cast<float*>(smraw + 23040);
    float*  feat  = reinterpret_cast<float*>(smraw + 23168);
    float*  stage = feat;   // raw logits [32][144] (reused before gather writes feat)

    const int t   = threadIdx.x;
    const int nb  = blockIdx.x * 32;
    const int b   = nb / kHW;
    const int hwb = nb - b * kHW;

    // load raw logits (contiguous) + mask
    for (int idx = t; idx < 2304; idx += 256) {
        const int px = idx / 72, j = idx - px * 72;
        stage[px * 144 + j]      = g_w_ctx[nb * 72 + idx];
        stage[px * 144 + 72 + j] = g_w_geo[nb * 72 + idx];
    }
    if (t < 32) msm[t] = mask[b * kHW + hwb + t];
    __syncthreads();

    // softmax over p for each (px, branch, group): 32*16 = 512 tasks (fp32 in, half out)
    for (int task = t; task < 512; task += 256) {
        const int px = task >> 4, bg = task & 15;
        const float* base = stage + px * 144 + (bg >> 3) * 72 + (bg & 7);
        __half* dst = wts + px * 144 + (bg >> 3) * 72 + (bg & 7);
        float mx = base[0];
        #pragma unroll
        for (int p = 1; p < kP; p++) mx = fmaxf(mx, base[p * 8]);
        float e[kP]; float s = 0.f;
        #pragma unroll
        for (int p = 0; p < kP; p++) { e[p] = __expf(base[p * 8] - mx); s += e[p]; }
        const float inv = 1.f / s;
        #pragma unroll
        for (int p = 0; p < kP; p++) dst[p * 8] = __float2half(e[p] * inv);
    }

    // bilinear corner precompute: 32*18 = 576 tasks
    for (int task = t; task < 576; task += 256) {
        const int px = task / 18, j = task - px * 18;
        const int br = j / 9, p = j - br * 9;
        const int n = nb + px;
        const float* kp = g_kp + br * (kN * kP * 2) + (n * kP + p) * 2;
        const float x = kp[0] * (float)kW - 0.5f;
        const float y = kp[1] * (float)kH - 0.5f;
        const float xf = floorf(x), yf = floorf(y);
        const float dx = x - xf, dy = y - yf;
        const int x0 = (int)xf, y0 = (int)yf;
        const int o = (px * 18 + j) * 4;
        #pragma unroll
        for (int c = 0; c < 4; c++) {
            const int xi = x0 + (c & 1), yi = y0 + (c >> 1);
            const bool valid = (xi >= 0) && (xi < kW) && (yi >= 0) && (yi < kH);
            const int xc = min(max(xi, 0), kW - 1), yc = min(max(yi, 0), kH - 1);
            const float wt = ((c & 1) ? dx : 1.f - dx) * ((c >> 1) ? dy : 1.f - dy);
            cw[o + c]   = valid ? wt : 0.f;
            cidx[o + c] = (short)(yc * kW + xc);
        }
    }
    __syncthreads();   // all stage reads done; feat may now be overwritten

    // phase 1: deformable gather (fp16 values).  t -> (pq 0..3, br 0..1, c4 0..31)
    {
        const int c4 = t & 31;
        const int br = (t >> 5) & 1;
        const int pq = t >> 6;
        const __half* vals = (br ? g_vals_geo : g_vals_ctx) + b * kHW * kC + c4 * 4;
        const int gidx = c4 >> 2;  // group = (c4*4)/16
        #pragma unroll
        for (int chunk = 0; chunk < 8; chunk++) {
            const int px = chunk * 4 + pq;
            float a0 = 0.f, a1 = 0.f, a2 = 0.f, a3 = 0.f;
            const __half* wtp = wts + px * 144 + br * 72 + gidx;
            const float* cwp = cw + (px * 18 + br * 9) * 4;
            const short* idp = cidx + (px * 18 + br * 9) * 4;
            #pragma unroll
            for (int p = 0; p < kP; p++) {
                const float wp = __half2float(wtp[p * 8]);
                #pragma unroll
                for (int c = 0; c < 4; c++) {
                    const float f = wp * cwp[p * 4 + c];
                    const H4 r = *reinterpret_cast<const H4*>(vals + (int)idp[p * 4 + c] * kC);
                    const float2 f0 = __half22float2(r.a);
                    const float2 f1 = __half22float2(r.b);
                    a0 = fmaf(f, f0.x, a0); a1 = fmaf(f, f0.y, a1);
                    a2 = fmaf(f, f1.x, a2); a3 = fmaf(f, f1.y, a3);
                }
            }
            const float sc = br ? 1.f : msm[px];
            float* fb = feat + (br * 128 + c4 * 4) * 33 + px;
            fb[0]  = a0 * sc; fb[33] = a1 * sc;
            fb[66] = a2 * sc; fb[99] = a3 * sc;
        }
    }
    __syncthreads();

    // phase 2: 256 -> 128 output conv, 4x4 register tiles
    {
        const int ty = t >> 3, tx = t & 7;
        const int o0 = ty * 4, px0 = tx * 4;
        float acc[4][4];
        #pragma unroll
        for (int i = 0; i < 4; i++)
            #pragma unroll
            for (int j = 0; j < 4; j++) acc[i][j] = 0.f;
        #pragma unroll 8
        for (int k = 0; k < 256; k++) {
            const float4 wv = *reinterpret_cast<const float4*>(g_OWT + k * 128 + o0);
            const float* fr = feat + k * 33 + px0;
            const float fa[4] = {fr[0], fr[1], fr[2], fr[3]};
            const float wa[4] = {wv.x, wv.y, wv.z, wv.w};
            #pragma unroll
            for (int i = 0; i < 4; i++)
                #pragma unroll
                for (int j = 0; j < 4; j++)
                    acc[i][j] = fmaf(wa[i], fa[j], acc[i][j]);
        }
        #pragma unroll
        for (int i = 0; i < 4; i++) {
            const float bb = out_b[o0 + i];
            *reinterpret_cast<float4*>(d_out + b * kC * kHW + (o0 + i) * kHW + hwb + px0) =
                make_float4(acc[i][0] + bb, acc[i][1] + bb, acc[i][2] + bb, acc[i][3] + bb);
        }
    }
}

// ---------------- launch ----------------
extern "C" void kernel_launch(void* const* d_in, const int* in_sizes, int n_in,
                              void* d_out, int out_size)
{
    const float* mask      = (const float*)d_in[0];
    const float* match     = (const float*)d_in[1];
    const float* context   = (const float*)d_in[2];
    const float* geometric = (const float*)d_in[3];
    const float* anc_c     = (const float*)d_in[4];
    const float* anc_g     = (const float*)d_in[5];
    const float* ln_g  = (const float*)d_in[6];
    const float* ln_b  = (const float*)d_in[7];
    const float* lnc_g = (const float*)d_in[8];
    const float* lnc_b = (const float*)d_in[9];
    const float* lng_g = (const float*)d_in[10];
    const float* lng_b = (const float*)d_in[11];
    const float* wc_w  = (const float*)d_in[12];
    const float* wc_b  = (const float*)d_in[13];
    const float* wg_w  = (const float*)d_in[14];
    const float* wg_b  = (const float*)d_in[15];
    const float* vc_w  = (const float*)d_in[16];
    const float* vc_b  = (const float*)d_in[17];
    const float* vg_w  = (const float*)d_in[18];
    const float* vg_b  = (const float*)d_in[19];
    const float* out_w = (const float*)d_in[20];
    const float* out_b = (const float*)d_in[21];
    const float* kpc_w = (const float*)d_in[22];
    const float* kpc_b = (const float*)d_in[23];
    const float* kpg_w = (const float*)d_in[24];
    const float* kpg_b = (const float*)d_in[25];
    float* out = (float*)d_out;

    cudaFuncSetAttribute(k1_ln_gemm, cudaFuncAttributeMaxDynamicSharedMemorySize, 50176);
    cudaFuncSetAttribute(k2_aggregate, cudaFuncAttributeMaxDynamicSharedMemorySize, kK2Smem);

    prep_weights<<<kOPAD, 128>>>(vc_w, vc_b, vg_w, vg_b, wc_w, wc_b, wg_w, wg_b,
                                 kpc_w, kpc_b, kpg_w, kpg_b,
                                 ln_g, ln_b, lnc_g, lnc_b, lng_g, lng_b);
    prep_outw<<<256, 128>>>(out_w);
    k1_ln_gemm<<<kN / 32, 256, 49920>>>(match, context, geometric, anc_c, anc_g, out, out_size);
    k2_aggregate<<<kN / 32, 256, kK2Smem>>>(mask, out_b, out);
}